// round 11
// baseline (speedup 1.0000x reference)
#include <cuda_runtime.h>
#include <cuda_fp16.h>

#define HIDDEN 128
#define NNODES 50000
#define NEDGES 640000

// Scratch (allocation-free rule: device globals)
__device__ __align__(16) __half g_ABh[NNODES * 256];  // per node: [A+bias1 (128) | B (128)], fp16

// ---------------------------------------------------------------------------
// Tensor-core GEMM with inline Z convert AND inline W1 pack (R6 design).
// AB = fp16(Z) @ fp16(W1 split). Block 64M x 256N, K=128 fully resident.
// 8 warps (2m x 4n), warp tile 32x64.
#define AS_ROW 136   // halves per A smem row: 128 data + 8 pad
#define BS_ROW 136   // halves per B smem row: 128 data + 8 pad
#define GEMM_SMEM ((64 * AS_ROW + 256 * BS_ROW) * 2)   // 87040 bytes

__device__ __forceinline__ void mma16816(float* d, unsigned a0, unsigned a1,
                                         unsigned a2, unsigned a3,
                                         unsigned b0, unsigned b1) {
    asm volatile(
        "mma.sync.aligned.m16n8k16.row.col.f32.f16.f16.f32 "
        "{%0,%1,%2,%3}, {%4,%5,%6,%7}, {%8,%9}, {%0,%1,%2,%3};"
        : "+f"(d[0]), "+f"(d[1]), "+f"(d[2]), "+f"(d[3])
        : "r"(a0), "r"(a1), "r"(a2), "r"(a3), "r"(b0), "r"(b1));
}

__global__ __launch_bounds__(256, 2) void gemm_kernel(const float* __restrict__ Z,
                                                      const float* __restrict__ W1,
                                                      const float* __restrict__ bias1) {
    extern __shared__ __half sm[];
    __half* As = sm;                   // [64][AS_ROW]
    __half* Bs = sm + 64 * AS_ROW;     // [256][BS_ROW]

    const int tid = threadIdx.x;
    const int m0 = blockIdx.x * 64;

    // ---- A tile LDG first (DRAM latency): 64 rows x 32 float4; 8/thread ----
    float4 va[8];
    #pragma unroll
    for (int i = 0; i < 8; i++) {
        int ch = tid + i * 256;
        int row = ch >> 5, c4 = ch & 31;
        int gr = m0 + row;
        if (gr < NNODES) va[i] = *(const float4*)(Z + (size_t)gr * HIDDEN + c4 * 4);
        else             va[i] = make_float4(0.f, 0.f, 0.f, 0.f);
    }

    // ---- B tile: W1 fp32 (L2-hot) -> cvt -> STS with row permutation ----
    // W1 flat [256][128]: src row 2j -> Bs row j (A-half), 2j+1 -> 128+j (B-half)
    #pragma unroll
    for (int bt = 0; bt < 4; bt++) {
        float4 vb[8];
        #pragma unroll
        for (int i = 0; i < 8; i++) {
            int ch = tid + (bt * 8 + i) * 256;
            vb[i] = *(const float4*)(W1 + (size_t)ch * 4);
        }
        #pragma unroll
        for (int i = 0; i < 8; i++) {
            int ch = tid + (bt * 8 + i) * 256;
            int s = ch >> 5, c4 = ch & 31;
            int n = (s & 1) ? 128 + (s >> 1) : (s >> 1);
            __half2* d2 = (__half2*)(Bs + n * BS_ROW + c4 * 4);
            d2[0] = __floats2half2_rn(vb[i].x, vb[i].y);
            d2[1] = __floats2half2_rn(vb[i].z, vb[i].w);
        }
    }

    // ---- A cvt + STS ----
    #pragma unroll
    for (int i = 0; i < 8; i++) {
        int ch = tid + i * 256;
        int row = ch >> 5, c4 = ch & 31;
        __half2* d2 = (__half2*)(As + row * AS_ROW + c4 * 4);
        d2[0] = __floats2half2_rn(va[i].x, va[i].y);
        d2[1] = __floats2half2_rn(va[i].z, va[i].w);
    }
    __syncthreads();

    const int wid = tid >> 5;
    const int lane = tid & 31;
    const int mbase = (wid >> 2) * 32;
    const int nbase = (wid & 3) * 64;
    const int g = lane >> 2;
    const int tq = lane & 3;
    const int row_l = lane & 15;
    const int a_hi = (lane >> 4) << 3;
    const int b_row = lane & 7;
    const int b_koff = ((lane >> 3) & 1) * 8;

    float acc[2][8][4];
    #pragma unroll
    for (int mi = 0; mi < 2; mi++)
        #pragma unroll
        for (int ni = 0; ni < 8; ni++)
            #pragma unroll
            for (int c = 0; c < 4; c++) acc[mi][ni][c] = 0.f;

    #pragma unroll
    for (int kc = 0; kc < 8; kc++) {
        unsigned a[2][4];
        #pragma unroll
        for (int mi = 0; mi < 2; mi++) {
            const __half* p = As + (mbase + mi * 16 + row_l) * AS_ROW + kc * 16 + a_hi;
            unsigned sa = (unsigned)__cvta_generic_to_shared(p);
            asm volatile("ldmatrix.sync.aligned.m8n8.x4.shared.b16 {%0,%1,%2,%3}, [%4];"
                         : "=r"(a[mi][0]), "=r"(a[mi][1]), "=r"(a[mi][2]), "=r"(a[mi][3])
                         : "r"(sa));
        }
        unsigned bf[8][2];
        #pragma unroll
        for (int ni = 0; ni < 8; ni++) {
            const __half* p = Bs + (nbase + ni * 8 + b_row) * BS_ROW + kc * 16 + b_koff;
            unsigned sb = (unsigned)__cvta_generic_to_shared(p);
            asm volatile("ldmatrix.sync.aligned.m8n8.x2.shared.b16 {%0,%1}, [%2];"
                         : "=r"(bf[ni][0]), "=r"(bf[ni][1])
                         : "r"(sb));
        }
        #pragma unroll
        for (int mi = 0; mi < 2; mi++)
            #pragma unroll
            for (int ni = 0; ni < 8; ni++)
                mma16816(acc[mi][ni], a[mi][0], a[mi][1], a[mi][2], a[mi][3],
                         bf[ni][0], bf[ni][1]);
    }

    // ---- epilogue: +bias1 on cols <128, fp16 store to g_ABh ----
    #pragma unroll
    for (int ni = 0; ni < 8; ni++) {
        int ncol = nbase + ni * 8 + tq * 2;
        float bx = 0.f, by = 0.f;
        if (ncol < 128) { bx = bias1[ncol]; by = bias1[ncol + 1]; }
        #pragma unroll
        for (int mi = 0; mi < 2; mi++) {
            int r0 = m0 + mbase + mi * 16 + g;
            if (r0 < NNODES) {
                *(__half2*)(g_ABh + (size_t)r0 * 256 + ncol) =
                    __floats2half2_rn(acc[mi][ni][0] + bx, acc[mi][ni][1] + by);
            }
            int r1 = r0 + 8;
            if (r1 < NNODES) {
                *(__half2*)(g_ABh + (size_t)r1 * 256 + ncol) =
                    __floats2half2_rn(acc[mi][ni][2] + bx, acc[mi][ni][3] + by);
            }
        }
    }
}

// ---------------------------------------------------------------------------
// Per-edge pass: 16 lanes per edge, 2 edges per warp (proven 32-reg shape),
// with software-pipelined index loads (next iteration's src/dst prefetched
// while current gathers/compute are in flight). Single-wave persistent grid.
// out[e] = bias2 + sum_j W2[j]*relu(A'[src][j]+B[dst][j])   (bias1 folded in A')
#define EDGE_BLOCKS 1184   // 148 SMs x 8 resident blocks: one wave

__global__ __launch_bounds__(256) void edge_kernel(
    const int* __restrict__ ei,
    const float* __restrict__ W2,
    const float* __restrict__ bias2,
    float* __restrict__ out)
{
    __shared__ int s_is64;
    if (threadIdx.x < 32) {
        unsigned m = __ballot_sync(0xffffffffu, ei[2 * threadIdx.x + 1] != 0);
        if (threadIdx.x == 0) s_is64 = (m == 0) ? 1 : 0;
    }

    const int lane = threadIdx.x & 31;
    const int sl = lane & 15;
    const int sub = lane >> 4;
    const int w = (blockIdx.x * blockDim.x + threadIdx.x) >> 5;
    const int nw = (EDGE_BLOCKS * 256) >> 5;
    const int estep = 2 * nw;

    const float4 w2a = *(const float4*)(W2 + sl * 8);
    const float4 w2b = *(const float4*)(W2 + sl * 8 + 4);
    const float b2 = bias2[0];
    const __half2 zero2 = __float2half2_rn(0.f);
    const long long* ei64 = (const long long*)ei;

    __syncthreads();
    const int is64 = s_is64;

    int e = 2 * w + sub;
    int src = 0, dst = 0;
    bool valid = (e < NEDGES);
    if (valid) {
        if (is64) {
            src = (int)__ldg(ei64 + e);
            dst = (int)__ldg(ei64 + NEDGES + e);
        } else {
            src = __ldg(ei + e);
            dst = __ldg(ei + NEDGES + e);
        }
    }

    while (valid) {
        // prefetch next iteration's indices
        const int en = e + estep;
        const bool vn = (en < NEDGES);
        int ns = 0, nd = 0;
        if (vn) {
            if (is64) {
                ns = (int)__ldg(ei64 + en);
                nd = (int)__ldg(ei64 + NEDGES + en);
            } else {
                ns = __ldg(ei + en);
                nd = __ldg(ei + NEDGES + en);
            }
        }

        uint4 av = *(const uint4*)(g_ABh + (size_t)src * 256 + sl * 8);
        uint4 bv = *(const uint4*)(g_ABh + (size_t)dst * 256 + 128 + sl * 8);
        const __half2* ah = (const __half2*)&av;
        const __half2* bh = (const __half2*)&bv;

        float2 f0 = __half22float2(__hmax2(__hadd2(ah[0], bh[0]), zero2));
        float2 f1 = __half22float2(__hmax2(__hadd2(ah[1], bh[1]), zero2));
        float2 f2 = __half22float2(__hmax2(__hadd2(ah[2], bh[2]), zero2));
        float2 f3 = __half22float2(__hmax2(__hadd2(ah[3], bh[3]), zero2));

        float acc = w2a.x * f0.x + w2a.y * f0.y + w2a.z * f1.x + w2a.w * f1.y
                  + w2b.x * f2.x + w2b.y * f2.y + w2b.z * f3.x + w2b.w * f3.y;

        acc += __shfl_xor_sync(0xffffffffu, acc, 1);
        acc += __shfl_xor_sync(0xffffffffu, acc, 2);
        acc += __shfl_xor_sync(0xffffffffu, acc, 4);
        acc += __shfl_xor_sync(0xffffffffu, acc, 8);

        if (sl == 0) out[e] = acc + b2;

        e = en;
        src = ns;
        dst = nd;
        valid = vn;
    }
}

// ---------------------------------------------------------------------------
extern "C" void kernel_launch(void* const* d_in, const int* in_sizes, int n_in,
                              void* d_out, int out_size) {
    const float* z     = (const float*)d_in[0];   // [50000,128]
    const float* W1    = (const float*)d_in[1];   // [128,256]
    const float* bias1 = (const float*)d_in[2];   // [128]
    const float* W2    = (const float*)d_in[3];   // [1,128]
    const float* bias2 = (const float*)d_in[4];   // [1]
    const int*   ei    = (const int*)d_in[5];     // [2,640000]
    float* out = (float*)d_out;

    static int smem_set = 0;
    if (!smem_set) {
        cudaFuncSetAttribute(gemm_kernel,
                             cudaFuncAttributeMaxDynamicSharedMemorySize, GEMM_SMEM);
        smem_set = 1;
    }

    gemm_kernel<<<(NNODES + 63) / 64, 256, GEMM_SMEM>>>(z, W1, bias1);

    edge_kernel<<<EDGE_BLOCKS, 256>>>(ei, W2, bias2, out);
}

// round 12
// speedup vs baseline: 1.8360x; 1.8360x over previous
#include <cuda_runtime.h>
#include <cuda_fp16.h>

#define HIDDEN 128
#define NNODES 50000
#define NEDGES 640000

// Scratch (allocation-free rule: device globals)
__device__ __align__(16) __half g_ABh[NNODES * 256];  // per node: [A+bias1 (128) | B (128)], fp16

// ---------------------------------------------------------------------------
// Tensor-core GEMM with inline Z convert AND inline W1 pack (R6 design).
// AB = fp16(Z) @ fp16(W1 split). Block 64M x 256N, K=128 fully resident.
// 8 warps (2m x 4n), warp tile 32x64.
#define AS_ROW 136   // halves per A smem row: 128 data + 8 pad
#define BS_ROW 136   // halves per B smem row: 128 data + 8 pad
#define GEMM_SMEM ((64 * AS_ROW + 256 * BS_ROW) * 2)   // 87040 bytes

__device__ __forceinline__ void mma16816(float* d, unsigned a0, unsigned a1,
                                         unsigned a2, unsigned a3,
                                         unsigned b0, unsigned b1) {
    asm volatile(
        "mma.sync.aligned.m16n8k16.row.col.f32.f16.f16.f32 "
        "{%0,%1,%2,%3}, {%4,%5,%6,%7}, {%8,%9}, {%0,%1,%2,%3};"
        : "+f"(d[0]), "+f"(d[1]), "+f"(d[2]), "+f"(d[3])
        : "r"(a0), "r"(a1), "r"(a2), "r"(a3), "r"(b0), "r"(b1));
}

__global__ __launch_bounds__(256, 2) void gemm_kernel(const float* __restrict__ Z,
                                                      const float* __restrict__ W1,
                                                      const float* __restrict__ bias1) {
    extern __shared__ __half sm[];
    __half* As = sm;                   // [64][AS_ROW]
    __half* Bs = sm + 64 * AS_ROW;     // [256][BS_ROW]

    const int tid = threadIdx.x;
    const int m0 = blockIdx.x * 64;

    // ---- A tile LDG first (DRAM latency): 64 rows x 32 float4; 8/thread ----
    float4 va[8];
    #pragma unroll
    for (int i = 0; i < 8; i++) {
        int ch = tid + i * 256;
        int row = ch >> 5, c4 = ch & 31;
        int gr = m0 + row;
        if (gr < NNODES) va[i] = *(const float4*)(Z + (size_t)gr * HIDDEN + c4 * 4);
        else             va[i] = make_float4(0.f, 0.f, 0.f, 0.f);
    }

    // ---- B tile: W1 fp32 (L2-hot) -> cvt -> STS with row permutation ----
    // W1 flat [256][128]: src row 2j -> Bs row j (A-half), 2j+1 -> 128+j (B-half)
    #pragma unroll
    for (int bt = 0; bt < 4; bt++) {
        float4 vb[8];
        #pragma unroll
        for (int i = 0; i < 8; i++) {
            int ch = tid + (bt * 8 + i) * 256;
            vb[i] = *(const float4*)(W1 + (size_t)ch * 4);
        }
        #pragma unroll
        for (int i = 0; i < 8; i++) {
            int ch = tid + (bt * 8 + i) * 256;
            int s = ch >> 5, c4 = ch & 31;
            int n = (s & 1) ? 128 + (s >> 1) : (s >> 1);
            __half2* d2 = (__half2*)(Bs + n * BS_ROW + c4 * 4);
            d2[0] = __floats2half2_rn(vb[i].x, vb[i].y);
            d2[1] = __floats2half2_rn(vb[i].z, vb[i].w);
        }
    }

    // ---- A cvt + STS ----
    #pragma unroll
    for (int i = 0; i < 8; i++) {
        int ch = tid + i * 256;
        int row = ch >> 5, c4 = ch & 31;
        __half2* d2 = (__half2*)(As + row * AS_ROW + c4 * 4);
        d2[0] = __floats2half2_rn(va[i].x, va[i].y);
        d2[1] = __floats2half2_rn(va[i].z, va[i].w);
    }
    __syncthreads();

    const int wid = tid >> 5;
    const int lane = tid & 31;
    const int mbase = (wid >> 2) * 32;
    const int nbase = (wid & 3) * 64;
    const int g = lane >> 2;
    const int tq = lane & 3;
    const int row_l = lane & 15;
    const int a_hi = (lane >> 4) << 3;
    const int b_row = lane & 7;
    const int b_koff = ((lane >> 3) & 1) * 8;

    float acc[2][8][4];
    #pragma unroll
    for (int mi = 0; mi < 2; mi++)
        #pragma unroll
        for (int ni = 0; ni < 8; ni++)
            #pragma unroll
            for (int c = 0; c < 4; c++) acc[mi][ni][c] = 0.f;

    #pragma unroll
    for (int kc = 0; kc < 8; kc++) {
        unsigned a[2][4];
        #pragma unroll
        for (int mi = 0; mi < 2; mi++) {
            const __half* p = As + (mbase + mi * 16 + row_l) * AS_ROW + kc * 16 + a_hi;
            unsigned sa = (unsigned)__cvta_generic_to_shared(p);
            asm volatile("ldmatrix.sync.aligned.m8n8.x4.shared.b16 {%0,%1,%2,%3}, [%4];"
                         : "=r"(a[mi][0]), "=r"(a[mi][1]), "=r"(a[mi][2]), "=r"(a[mi][3])
                         : "r"(sa));
        }
        unsigned bf[8][2];
        #pragma unroll
        for (int ni = 0; ni < 8; ni++) {
            const __half* p = Bs + (nbase + ni * 8 + b_row) * BS_ROW + kc * 16 + b_koff;
            unsigned sb = (unsigned)__cvta_generic_to_shared(p);
            asm volatile("ldmatrix.sync.aligned.m8n8.x2.shared.b16 {%0,%1}, [%2];"
                         : "=r"(bf[ni][0]), "=r"(bf[ni][1])
                         : "r"(sb));
        }
        #pragma unroll
        for (int mi = 0; mi < 2; mi++)
            #pragma unroll
            for (int ni = 0; ni < 8; ni++)
                mma16816(acc[mi][ni], a[mi][0], a[mi][1], a[mi][2], a[mi][3],
                         bf[ni][0], bf[ni][1]);
    }

    // ---- epilogue: +bias1 on cols <128, fp16 store to g_ABh ----
    #pragma unroll
    for (int ni = 0; ni < 8; ni++) {
        int ncol = nbase + ni * 8 + tq * 2;
        float bx = 0.f, by = 0.f;
        if (ncol < 128) { bx = bias1[ncol]; by = bias1[ncol + 1]; }
        #pragma unroll
        for (int mi = 0; mi < 2; mi++) {
            int r0 = m0 + mbase + mi * 16 + g;
            if (r0 < NNODES) {
                *(__half2*)(g_ABh + (size_t)r0 * 256 + ncol) =
                    __floats2half2_rn(acc[mi][ni][0] + bx, acc[mi][ni][1] + by);
            }
            int r1 = r0 + 8;
            if (r1 < NNODES) {
                *(__half2*)(g_ABh + (size_t)r1 * 256 + ncol) =
                    __floats2half2_rn(acc[mi][ni][2] + bx, acc[mi][ni][3] + by);
            }
        }
    }
}

// ---------------------------------------------------------------------------
// Per-edge pass (proven R6/R8 shape): 16 lanes/edge, 2 edges/warp, grid 2368,
// 32 regs, grid-stride. Streaming cache hints: indices via __ldcs (touch-once,
// keep L1 for g_ABh gathers), output via st.global.cs.
// out[e] = bias2 + sum_j W2[j]*relu(A'[src][j]+B[dst][j])   (bias1 folded in A')
__global__ __launch_bounds__(256) void edge_kernel(
    const int* __restrict__ ei,
    const float* __restrict__ W2,
    const float* __restrict__ bias2,
    float* __restrict__ out)
{
    __shared__ int s_is64;
    if (threadIdx.x < 32) {
        unsigned m = __ballot_sync(0xffffffffu, ei[2 * threadIdx.x + 1] != 0);
        if (threadIdx.x == 0) s_is64 = (m == 0) ? 1 : 0;
    }

    const int lane = threadIdx.x & 31;
    const int sl = lane & 15;
    const int sub = lane >> 4;
    const int w = (blockIdx.x * blockDim.x + threadIdx.x) >> 5;
    const int nw = (gridDim.x * blockDim.x) >> 5;

    const float4 w2a = *(const float4*)(W2 + sl * 8);
    const float4 w2b = *(const float4*)(W2 + sl * 8 + 4);
    const float b2 = bias2[0];
    const __half2 zero2 = __float2half2_rn(0.f);
    const long long* ei64 = (const long long*)ei;

    __syncthreads();
    const int is64 = s_is64;

    for (int base = 2 * w; base < NEDGES; base += 2 * nw) {
        const int e = base + sub;
        int src, dst;
        if (is64) {
            src = (int)__ldcs(ei64 + e);
            dst = (int)__ldcs(ei64 + NEDGES + e);
        } else {
            src = __ldcs(ei + e);
            dst = __ldcs(ei + NEDGES + e);
        }
        uint4 av = *(const uint4*)(g_ABh + (size_t)src * 256 + sl * 8);
        uint4 bv = *(const uint4*)(g_ABh + (size_t)dst * 256 + 128 + sl * 8);
        const __half2* ah = (const __half2*)&av;
        const __half2* bh = (const __half2*)&bv;

        float2 f0 = __half22float2(__hmax2(__hadd2(ah[0], bh[0]), zero2));
        float2 f1 = __half22float2(__hmax2(__hadd2(ah[1], bh[1]), zero2));
        float2 f2 = __half22float2(__hmax2(__hadd2(ah[2], bh[2]), zero2));
        float2 f3 = __half22float2(__hmax2(__hadd2(ah[3], bh[3]), zero2));

        float acc = w2a.x * f0.x + w2a.y * f0.y + w2a.z * f1.x + w2a.w * f1.y
                  + w2b.x * f2.x + w2b.y * f2.y + w2b.z * f3.x + w2b.w * f3.y;

        acc += __shfl_xor_sync(0xffffffffu, acc, 1);
        acc += __shfl_xor_sync(0xffffffffu, acc, 2);
        acc += __shfl_xor_sync(0xffffffffu, acc, 4);
        acc += __shfl_xor_sync(0xffffffffu, acc, 8);

        if (sl == 0) {
            float v = acc + b2;
            asm volatile("st.global.cs.f32 [%0], %1;" :: "l"(out + e), "f"(v) : "memory");
        }
    }
}

// ---------------------------------------------------------------------------
extern "C" void kernel_launch(void* const* d_in, const int* in_sizes, int n_in,
                              void* d_out, int out_size) {
    const float* z     = (const float*)d_in[0];   // [50000,128]
    const float* W1    = (const float*)d_in[1];   // [128,256]
    const float* bias1 = (const float*)d_in[2];   // [128]
    const float* W2    = (const float*)d_in[3];   // [1,128]
    const float* bias2 = (const float*)d_in[4];   // [1]
    const int*   ei    = (const int*)d_in[5];     // [2,640000]
    float* out = (float*)d_out;

    static int smem_set = 0;
    if (!smem_set) {
        cudaFuncSetAttribute(gemm_kernel,
                             cudaFuncAttributeMaxDynamicSharedMemorySize, GEMM_SMEM);
        smem_set = 1;
    }

    gemm_kernel<<<(NNODES + 63) / 64, 256, GEMM_SMEM>>>(z, W1, bias1);

    edge_kernel<<<2368, 256>>>(ei, W2, bias2, out);
}